// round 2
// baseline (speedup 1.0000x reference)
#include <cuda_runtime.h>

#define T_STEPS 512
#define BATCH   512
#define INDIM   4
#define AUXDIM  28
#define OUTDIM  32
#define GDIM    64
#define NCTA    64
#define BC      8          // batch rows per CTA
#define NTHREADS 640
#define JCOLS   1184       // 1024 (W_r) | 128 (W_i) | 32 (W_o)
#define JPAIRS  592

typedef unsigned long long ull;

// ---------------- device globals (scratch; no allocation allowed) -------------
__device__ float g_W[64 * JCOLS];          // [k][j] transposed packed weights
__device__ float g_bias[JCOLS];
__device__ float g_expWs[32 * 64];         // exp(W_s)[o][g]
__device__ float g_ov0base[64];            // sum_o b0[o]*exp(W_s)[o][g]
__device__ float g_sigWrT[64 * 32];        // sigmoid(W_rm^T)[k][j]
__device__ float g_part[(T_STEPS + 1) * NCTA];
__device__ unsigned int g_ctr[T_STEPS + 1];

__device__ __forceinline__ void ffma2(ull &d, ull a, ull b) {
    asm volatile("fma.rn.f32x2 %0, %1, %2, %0;" : "+l"(d) : "l"(a), "l"(b));
}
__device__ __forceinline__ float wsum32(float v) {
#pragma unroll
    for (int s = 16; s; s >>= 1) v += __shfl_xor_sync(0xffffffffu, v, s);
    return v;
}
__device__ __forceinline__ float sigmoidf_(float x) { return 1.f / (1.f + expf(-x)); }

// ---------------- prep kernel: transpose/pack weights, reset sync state -------
__global__ void prep_kernel(const float* __restrict__ Wi, const float* __restrict__ bi,
                            const float* __restrict__ Wr, const float* __restrict__ br,
                            const float* __restrict__ Wo, const float* __restrict__ bo,
                            const float* __restrict__ Ws, const float* __restrict__ Wrm,
                            const float* __restrict__ b0) {
    int idx = blockIdx.x * blockDim.x + threadIdx.x;
    int stride = gridDim.x * blockDim.x;
    for (int i = idx; i < 64 * JCOLS; i += stride) {
        int k = i / JCOLS, j = i % JCOLS;
        float v;
        if (j < 1024)       v = Wr[j * 64 + k];
        else if (j < 1152)  v = Wi[(j - 1024) * 64 + k];
        else                v = Wo[(j - 1152) * 64 + k];
        g_W[k * JCOLS + j] = v;
    }
    for (int j = idx; j < JCOLS; j += stride)
        g_bias[j] = (j < 1024) ? br[j] : ((j < 1152) ? bi[j - 1024] : bo[j - 1152]);
    for (int i = idx; i < 32 * 64; i += stride) g_expWs[i] = expf(Ws[i]);
    for (int i = idx; i < 64 * 32; i += stride) {
        int k = i / 32, j = i % 32;
        g_sigWrT[i] = 1.f / (1.f + expf(-Wrm[j * 64 + k]));
    }
    for (int g = idx; g < 64; g += stride) {
        float s = 0.f;
        for (int o = 0; o < 32; o++) s += b0[o] * expf(Ws[o * 64 + g]);
        g_ov0base[g] = s;
    }
    for (int i = idx; i <= T_STEPS; i += stride) g_ctr[i] = (i == 0) ? (unsigned)NCTA : 0u;
    for (int i = idx; i < NCTA; i += stride) g_part[i] = 0.f;
}

// ---------------- persistent recurrent kernel --------------------------------
__global__ void __launch_bounds__(NTHREADS, 1) lstm_kernel(
    const float* __restrict__ xm, const float* __restrict__ xa,
    const float* __restrict__ lng, const float* __restrict__ lnb,
    float* __restrict__ out) {
    __shared__ __align__(16) float2 s_featD[64][8];  // dup-packed feat^T [k][b]
    __shared__ float s_c[8][32];
    __shared__ float s_P[8][1024];
    __shared__ float s_I[8][128];
    __shared__ float s_go[8][32];
    __shared__ float s_tov0[8][64];
    __shared__ float s_ov1[8][32];
    __shared__ float s_m1[8][32];
    __shared__ float s_m2[8][32];
    __shared__ float s_abs[8];
    __shared__ float s_invS;

    const int tid  = threadIdx.x;
    const int cta  = blockIdx.x;
    const int lane = tid & 31;
    const int warp = tid >> 5;

    for (int i = tid; i < 8 * 32; i += NTHREADS) ((float*)s_c)[i] = 0.f;

    const int  jp = tid;
    const bool gemm_active = (jp < JPAIRS);
    const float* wcol = g_W + 2 * jp;
    float bias0 = 0.f, bias1 = 0.f;
    if (gemm_active) { bias0 = g_bias[2 * jp]; bias1 = g_bias[2 * jp + 1]; }

    const int fb_k = tid >> 3, fb_b = tid & 7;   // feat build (tid<512)
    const int ov_b = tid >> 6, ov_g = tid & 63;  // ov0 raw    (tid<512)
    const int o1_b = tid >> 5;                   // ov1 gemm   (tid<256), j=lane

    float r_lng = 0.f, r_lnb = 0.f;
    if (warp < 8) { r_lng = lng[lane]; r_lnb = lnb[lane]; }

    // preload x for t=0
    float rx = 0.f;
    const int gb = cta * BC + fb_b;
    if (tid < 512 && fb_k < 32) {
        rx = (fb_k < INDIM) ? xm[(size_t)gb * INDIM + fb_k]
                            : xa[(size_t)gb * AUXDIM + (fb_k - INDIM)];
    }

    const size_t OSZ = (size_t)T_STEPS * BATCH * OUTDIM;
    float* out_h  = out;
    float* out_c  = out + OSZ;
    float* out_o  = out + 2 * OSZ;
    float* out_mr = out + 3 * OSZ;
    float* out_op = out + 4 * OSZ;
    float* out_mf = out + 5 * OSZ;
    float* out_of = out + 6 * OSZ;

    __syncthreads();

    for (int t = 0; t < T_STEPS; t++) {
        // P0: build dup-packed feat^T. k<32: x inputs; k>=32: RAW carry c.
        if (tid < 512) {
            float v = (fb_k < 32) ? rx : s_c[fb_b][fb_k - 32];
            s_featD[fb_k][fb_b] = make_float2(v, v);
        }
        __syncthreads();

        // P1: big GEMM, K split: accA = x-part, accB = c-part (f32x2, 2 cols x 8 rows)
        ull accA[8], accB[8];
        if (gemm_active) {
#pragma unroll
            for (int b = 0; b < 8; b++) { accA[b] = 0ull; accB[b] = 0ull; }
#pragma unroll 8
            for (int k = 0; k < 32; k++) {
                ull w = *(const ull*)(wcol + k * JCOLS);
                const longlong2* f = (const longlong2*)(&s_featD[k][0]);
                longlong2 f01 = f[0], f23 = f[1], f45 = f[2], f67 = f[3];
                ffma2(accA[0], w, (ull)f01.x); ffma2(accA[1], w, (ull)f01.y);
                ffma2(accA[2], w, (ull)f23.x); ffma2(accA[3], w, (ull)f23.y);
                ffma2(accA[4], w, (ull)f45.x); ffma2(accA[5], w, (ull)f45.y);
                ffma2(accA[6], w, (ull)f67.x); ffma2(accA[7], w, (ull)f67.y);
            }
#pragma unroll 8
            for (int k = 32; k < 64; k++) {
                ull w = *(const ull*)(wcol + k * JCOLS);
                const longlong2* f = (const longlong2*)(&s_featD[k][0]);
                longlong2 f01 = f[0], f23 = f[1], f45 = f[2], f67 = f[3];
                ffma2(accB[0], w, (ull)f01.x); ffma2(accB[1], w, (ull)f01.y);
                ffma2(accB[2], w, (ull)f23.x); ffma2(accB[3], w, (ull)f23.y);
                ffma2(accB[4], w, (ull)f45.x); ffma2(accB[5], w, (ull)f45.y);
                ffma2(accB[6], w, (ull)f67.x); ffma2(accB[7], w, (ull)f67.y);
            }
        }
        // ov0 raw: c @ exp(W_s)  (one output per thread, tid<512)
        float accC = 0.f;
        if (tid < 512) {
#pragma unroll 8
            for (int o = 0; o < 32; o++) accC += s_c[ov_b][o] * g_expWs[o * 64 + ov_g];
        }
        // prefetch next step's x (hidden under the wait below)
        if (tid < 512 && fb_k < 32 && t + 1 < T_STEPS) {
            rx = (fb_k < INDIM)
                     ? xm[(size_t)(t + 1) * BATCH * INDIM + (size_t)gb * INDIM + fb_k]
                     : xa[(size_t)(t + 1) * BATCH * AUXDIM + (size_t)gb * AUXDIM + (fb_k - INDIM)];
        }
        // global scalar sync: wait for all CTAs' |c| partials of step t (deterministic sum)
        if (warp == 0) {
            if (lane == 0) {
                while (((volatile unsigned int*)g_ctr)[t] < (unsigned)NCTA) {}
            }
            __syncwarp();
            __threadfence();
            volatile float* pp = g_part + (size_t)t * NCTA;
            float v = pp[lane] + pp[lane + 32];
            v = wsum32(v);
            if (lane == 0) s_invS = 1.f / (v + 1e-5f);
        }
        __syncthreads();
        const float invS = s_invS;

        // Epilogue: logits = accA + invS*accB + bias, activation by column range
        if (gemm_active) {
            const int j0 = 2 * jp;
#pragma unroll
            for (int b = 0; b < 8; b++) {
                float2 a  = *(float2*)&accA[b];
                float2 bb = *(float2*)&accB[b];
                float v0 = fmaf(invS, bb.x, a.x) + bias0;
                float v1 = fmaf(invS, bb.y, a.y) + bias1;
                if (j0 < 1024) {
                    s_P[b][j0]     = fmaxf(v0, 0.f);
                    s_P[b][j0 + 1] = fmaxf(v1, 0.f);
                } else if (j0 < 1152) {
                    s_I[b][j0 - 1024] = sigmoidf_(v0);
                    s_I[b][j0 - 1023] = sigmoidf_(v1);
                } else {
                    s_go[b][j0 - 1152] = sigmoidf_(v0);
                    s_go[b][j0 - 1151] = sigmoidf_(v1);
                }
            }
        }
        if (tid < 512)
            s_tov0[ov_b][ov_g] = tanhf(fmaf(invS, accC, -g_ov0base[ov_g]));
        __syncthreads();

        // P2/P3 (all in one phase): ov1 gemm | r-norm+einsum | i-norm+einsum
        if (warp < 8) {
            float acc = 0.f;
#pragma unroll 8
            for (int k = 0; k < 64; k++) acc += s_tov0[o1_b][k] * g_sigWrT[k * 32 + lane];
            s_ov1[o1_b][lane] = acc;
        } else if (warp < 16) {
            const int b = warp - 8;
            float m2 = 0.f;
            for (int o = 0; o < 32; o++) {
                float v  = s_P[b][o * 32 + lane];
                float rs = wsum32(v);
                m2 += v * (s_c[b][o] / fmaxf(rs, 1e-12f));
            }
            s_m2[b][lane] = m2;
        } else {
            const int wloc = warp - 16;
#pragma unroll
            for (int bb2 = 0; bb2 < 2; bb2++) {
                const int b = wloc * 2 + bb2;
                float m1 = 0.f;
#pragma unroll
                for (int ii = 0; ii < 4; ii++) {
                    float v  = s_I[b][ii * 32 + lane];
                    float rs = wsum32(v);
                    m1 += s_featD[ii][b].x * v / fmaxf(rs, 1e-12f);
                }
                s_m1[b][lane] = m1;
            }
        }
        __syncthreads();

        // P4: combine, MR gate, LN, outputs, new carry
        if (warp < 8) {
            const int b = warp;
            float mn = s_m1[b][lane] + s_m2[b][lane];
            float o  = s_go[b][lane];
            float f  = 1.f - o;
            float x  = s_ov1[b][lane];
            float mu = wsum32(x) * (1.f / 32.f);
            float d  = x - mu;
            float var = wsum32(d * d) * (1.f / 32.f);
            float ln  = d * rsqrtf(var + 1e-5f) * r_lng + r_lnb;
            float ov2 = ln - fmaxf(ln - f, 0.f);
            float MR  = fmaxf(ov2 + 1.f - f, 0.f) + f - 1.f;
            float op  = o + MR;
            float h   = o * mn;
            float cn  = (1.f - op) * mn;
            float mf  = MR * mn;
            size_t idx = (size_t)t * BATCH * OUTDIM + (size_t)(cta * BC + b) * OUTDIM + lane;
            out_h[idx] = h;  out_c[idx] = cn; out_o[idx] = o;  out_mr[idx] = MR;
            out_op[idx] = op; out_mf[idx] = mf; out_of[idx] = h;
            s_c[b][lane] = cn;
            float as = wsum32(fabsf(cn));
            if (lane == 0) s_abs[b] = as;
        }
        __syncthreads();
        // post this CTA's |c_new| partial for step t+1 (overlapped with next GEMM)
        if (tid == 0) {
            float p = 0.f;
#pragma unroll
            for (int b = 0; b < 8; b++) p += s_abs[b];
            g_part[(size_t)(t + 1) * NCTA + cta] = p;
            __threadfence();
            atomicAdd(&g_ctr[t + 1], 1u);
        }
    }
}

// ---------------- launch ------------------------------------------------------
extern "C" void kernel_launch(void* const* d_in, const int* in_sizes, int n_in,
                              void* d_out, int out_size) {
    const float* xm  = (const float*)d_in[0];
    const float* xa  = (const float*)d_in[1];
    const float* Wi  = (const float*)d_in[2];
    const float* bi  = (const float*)d_in[3];
    const float* Wr  = (const float*)d_in[4];
    const float* br  = (const float*)d_in[5];
    const float* Wo  = (const float*)d_in[6];
    const float* bo  = (const float*)d_in[7];
    const float* Ws  = (const float*)d_in[8];
    const float* Wrm = (const float*)d_in[9];
    const float* b0  = (const float*)d_in[10];
    const float* lng = (const float*)d_in[11];
    const float* lnb = (const float*)d_in[12];
    (void)in_sizes; (void)n_in; (void)out_size;

    prep_kernel<<<128, 256>>>(Wi, bi, Wr, br, Wo, bo, Ws, Wrm, b0);
    lstm_kernel<<<NCTA, NTHREADS>>>(xm, xa, lng, lnb, (float*)d_out);
}

// round 7
// speedup vs baseline: 1.1303x; 1.1303x over previous
#include <cuda_runtime.h>

#define T_STEPS 512
#define BATCH   512
#define INDIM   4
#define AUXDIM  28
#define OUTDIM  32
#define GDIM    64
#define NCTA    64
#define BC      8          // batch rows per CTA
#define NTHREADS 640
#define JCOLS   1184       // 1024 (W_r) | 128 (W_i) | 32 (W_o)
#define JPAIRS  592
#define CACHED_JP 288      // jp < 288 -> caching loads (576 cols = 147KB, L1-resident)

typedef unsigned long long ull;

// ---------------- device globals (scratch; no allocation allowed) -------------
__device__ __align__(16) float g_W[64 * JCOLS];  // [k][j] transposed packed weights
__device__ float g_bias[JCOLS];
__device__ float g_expWs[32 * 64];         // exp(W_s)[o][g]
__device__ float g_ov0base[64];            // sum_o b0[o]*exp(W_s)[o][g]
__device__ float g_sigWrT[64 * 32];        // sigmoid(W_rm^T)[k][j]
__device__ __align__(16) ull g_slot[(T_STEPS + 1) * NCTA];  // (tag<<32)|float-bits

__device__ __forceinline__ void ffma2(ull &d, ull a, ull b) {
    asm volatile("fma.rn.f32x2 %0, %1, %2, %0;" : "+l"(d) : "l"(a), "l"(b));
}
__device__ __forceinline__ float wsum32(float v) {
#pragma unroll
    for (int s = 16; s; s >>= 1) v += __shfl_xor_sync(0xffffffffu, v, s);
    return v;
}
__device__ __forceinline__ float sigmoidf_(float x) { return 1.f / (1.f + expf(-x)); }

// Morally-strong relaxed gpu-scope ops: PTX guarantees single-copy atomicity
// and coherent visibility for strong scoped ops (weak .cg has NO such
// guarantee -> tag/value tearing was the round-3/5/6 corruption). Relaxed
// lowers to a single LDG/STG.STRONG.GPU: no fence, no CCTL.IVALL L1 flush.
__device__ __forceinline__ float wait_slot(const ull* p, unsigned tag) {
    ull v;
    do {
        asm volatile("ld.relaxed.gpu.global.u64 %0, [%1];"
                     : "=l"(v) : "l"(p) : "memory");
    } while ((unsigned)(v >> 32) != tag);
    return __uint_as_float((unsigned)v);
}
__device__ __forceinline__ void post_slot(ull* p, ull pk) {
    asm volatile("st.relaxed.gpu.global.u64 [%0], %1;"
                 :: "l"(p), "l"(pk) : "memory");
}

// ---------------- prep kernel: transpose/pack weights, reset sync state -------
__global__ void prep_kernel(const float* __restrict__ Wi, const float* __restrict__ bi,
                            const float* __restrict__ Wr, const float* __restrict__ br,
                            const float* __restrict__ Wo, const float* __restrict__ bo,
                            const float* __restrict__ Ws, const float* __restrict__ Wrm,
                            const float* __restrict__ b0) {
    int idx = blockIdx.x * blockDim.x + threadIdx.x;
    int stride = gridDim.x * blockDim.x;
    for (int i = idx; i < 64 * JCOLS; i += stride) {
        int k = i / JCOLS, j = i % JCOLS;
        float v;
        if (j < 1024)       v = Wr[j * 64 + k];
        else if (j < 1152)  v = Wi[(j - 1024) * 64 + k];
        else                v = Wo[(j - 1152) * 64 + k];
        g_W[k * JCOLS + j] = v;
    }
    for (int j = idx; j < JCOLS; j += stride)
        g_bias[j] = (j < 1024) ? br[j] : ((j < 1152) ? bi[j - 1024] : bo[j - 1152]);
    for (int i = idx; i < 32 * 64; i += stride) g_expWs[i] = expf(Ws[i]);
    for (int i = idx; i < 64 * 32; i += stride) {
        int k = i / 32, j = i % 32;
        g_sigWrT[i] = 1.f / (1.f + expf(-Wrm[j * 64 + k]));
    }
    for (int g = idx; g < 64; g += stride) {
        float s = 0.f;
        for (int o = 0; o < 32; o++) s += b0[o] * expf(Ws[o * 64 + g]);
        g_ov0base[g] = s;
    }
    // reset ALL slots (stale tags from a previous graph replay would alias
    // valid tags), then arm step 0 with partial |c| = 0, tag = 1.
    for (int i = idx; i < (T_STEPS + 1) * NCTA; i += stride) g_slot[i] = 0ull;
    for (int i = idx; i < NCTA; i += stride) g_slot[i] = (1ull << 32);
}

// ---------------- GEMM inner loop (round-2 structure, CG split) --------------
template<bool CG>
__device__ __forceinline__ void run_gemm(const float* __restrict__ wcol,
                                         const float2* __restrict__ sfD,
                                         ull accA[8], ull accB[8]) {
#pragma unroll 8
    for (int k = 0; k < 32; k++) {
        const float* p = wcol + k * JCOLS;
        ull w = CG ? __ldcg((const ull*)p) : *(const ull*)p;
        const longlong2* f = (const longlong2*)(sfD + k * 8);
        longlong2 f01 = f[0], f23 = f[1], f45 = f[2], f67 = f[3];
        ffma2(accA[0], w, (ull)f01.x); ffma2(accA[1], w, (ull)f01.y);
        ffma2(accA[2], w, (ull)f23.x); ffma2(accA[3], w, (ull)f23.y);
        ffma2(accA[4], w, (ull)f45.x); ffma2(accA[5], w, (ull)f45.y);
        ffma2(accA[6], w, (ull)f67.x); ffma2(accA[7], w, (ull)f67.y);
    }
#pragma unroll 8
    for (int k = 32; k < 64; k++) {
        const float* p = wcol + k * JCOLS;
        ull w = CG ? __ldcg((const ull*)p) : *(const ull*)p;
        const longlong2* f = (const longlong2*)(sfD + k * 8);
        longlong2 f01 = f[0], f23 = f[1], f45 = f[2], f67 = f[3];
        ffma2(accB[0], w, (ull)f01.x); ffma2(accB[1], w, (ull)f01.y);
        ffma2(accB[2], w, (ull)f23.x); ffma2(accB[3], w, (ull)f23.y);
        ffma2(accB[4], w, (ull)f45.x); ffma2(accB[5], w, (ull)f45.y);
        ffma2(accB[6], w, (ull)f67.x); ffma2(accB[7], w, (ull)f67.y);
    }
}

// ---------------- persistent recurrent kernel --------------------------------
__global__ void __launch_bounds__(NTHREADS, 1) lstm_kernel(
    const float* __restrict__ xm, const float* __restrict__ xa,
    const float* __restrict__ lng, const float* __restrict__ lnb,
    float* __restrict__ out) {
    __shared__ __align__(16) float2 s_featD[64][8];  // dup-packed feat^T [k][b]
    __shared__ float s_c[8][32];
    __shared__ float s_P[8][1024];
    __shared__ float s_I[8][128];
    __shared__ float s_go[8][32];
    __shared__ float s_tov0[8][64];
    __shared__ float s_ov1[8][32];
    __shared__ float s_m1[8][32];
    __shared__ float s_m2[8][32];
    __shared__ float s_abs[8];
    __shared__ float s_invS;

    const int tid  = threadIdx.x;
    const int cta  = blockIdx.x;
    const int lane = tid & 31;
    const int warp = tid >> 5;

    for (int i = tid; i < 8 * 32; i += NTHREADS) ((float*)s_c)[i] = 0.f;

    const int  jp = tid;
    const bool gemm_active = (jp < JPAIRS);
    const float* wcol = g_W + 2 * jp;
    float bias0 = 0.f, bias1 = 0.f;
    if (gemm_active) { bias0 = g_bias[2 * jp]; bias1 = g_bias[2 * jp + 1]; }

    const int fb_k = tid >> 3, fb_b = tid & 7;   // feat build (tid<512)
    const int ov_b = tid >> 6, ov_g = tid & 63;  // ov0 raw    (tid<512)

    float r_lng = 0.f, r_lnb = 0.f;
    if (warp < 8) { r_lng = lng[lane]; r_lnb = lnb[lane]; }

    // preload x for t=0
    float rx = 0.f;
    const int gb = cta * BC + fb_b;
    if (tid < 512 && fb_k < 32) {
        rx = (fb_k < INDIM) ? xm[(size_t)gb * INDIM + fb_k]
                            : xa[(size_t)gb * AUXDIM + (fb_k - INDIM)];
    }

    const size_t OSZ = (size_t)T_STEPS * BATCH * OUTDIM;
    float* out_h  = out;
    float* out_c  = out + OSZ;
    float* out_o  = out + 2 * OSZ;
    float* out_mr = out + 3 * OSZ;
    float* out_op = out + 4 * OSZ;
    float* out_mf = out + 5 * OSZ;
    float* out_of = out + 6 * OSZ;

    __syncthreads();

    for (int t = 0; t < T_STEPS; t++) {
        // P0: build dup-packed feat^T. k<32: x inputs; k>=32: RAW carry c.
        if (tid < 512) {
            float v = (fb_k < 32) ? rx : s_c[fb_b][fb_k - 32];
            s_featD[fb_k][fb_b] = make_float2(v, v);
        }
        __syncthreads();

        // P1: big GEMM, K split: accA = x-part, accB = c-part (f32x2, 2 cols x 8 rows)
        ull accA[8], accB[8];
        if (gemm_active) {
#pragma unroll
            for (int b = 0; b < 8; b++) { accA[b] = 0ull; accB[b] = 0ull; }
            if (jp < CACHED_JP) run_gemm<false>(wcol, &s_featD[0][0], accA, accB);
            else                run_gemm<true >(wcol, &s_featD[0][0], accA, accB);
        }
        // ov0 raw: c @ exp(W_s)  (one output per thread, tid<512)
        float accC = 0.f;
        if (tid < 512) {
#pragma unroll 8
            for (int o = 0; o < 32; o++) accC += s_c[ov_b][o] * g_expWs[o * 64 + ov_g];
        }
        // prefetch next step's x (hidden under the wait below)
        if (tid < 512 && fb_k < 32 && t + 1 < T_STEPS) {
            rx = (fb_k < INDIM)
                     ? xm[(size_t)(t + 1) * BATCH * INDIM + (size_t)gb * INDIM + fb_k]
                     : xa[(size_t)(t + 1) * BATCH * AUXDIM + (size_t)gb * AUXDIM + (fb_k - INDIM)];
        }
        // global scalar sync: strong relaxed.gpu tagged handshake
        if (warp == 0) {
            const unsigned tag = (unsigned)(t + 1);
            const ull* base = g_slot + (size_t)t * NCTA;
            float p0 = wait_slot(base + lane, tag);
            float p1 = wait_slot(base + lane + 32, tag);
            float v = wsum32(p0 + p1);
            if (lane == 0) s_invS = 1.f / (v + 1e-5f);
        }
        __syncthreads();
        const float invS = s_invS;

        // Epilogue: logits = accA + invS*accB + bias, activation by column range
        if (gemm_active) {
            const int j0 = 2 * jp;
#pragma unroll
            for (int b = 0; b < 8; b++) {
                float2 a  = *(float2*)&accA[b];
                float2 bb = *(float2*)&accB[b];
                float v0 = fmaf(invS, bb.x, a.x) + bias0;
                float v1 = fmaf(invS, bb.y, a.y) + bias1;
                if (j0 < 1024) {
                    s_P[b][j0]     = fmaxf(v0, 0.f);
                    s_P[b][j0 + 1] = fmaxf(v1, 0.f);
                } else if (j0 < 1152) {
                    s_I[b][j0 - 1024] = sigmoidf_(v0);
                    s_I[b][j0 - 1023] = sigmoidf_(v1);
                } else {
                    s_go[b][j0 - 1152] = sigmoidf_(v0);
                    s_go[b][j0 - 1151] = sigmoidf_(v1);
                }
            }
        }
        if (tid < 512)
            s_tov0[ov_b][ov_g] = tanhf(fmaf(invS, accC, -g_ov0base[ov_g]));
        __syncthreads();

        // P2/P3 (all in one phase): ov1 gemm | r-norm+einsum | i-norm+einsum
        if (warp < 8) {
            const int b = warp;
            float acc = 0.f;
#pragma unroll 8
            for (int k = 0; k < 64; k++) acc += s_tov0[b][k] * g_sigWrT[k * 32 + lane];
            s_ov1[b][lane] = acc;
        } else if (warp < 16) {
            const int b = warp - 8;
            float m2 = 0.f;
            for (int o = 0; o < 32; o++) {
                float v  = s_P[b][o * 32 + lane];
                float rs = wsum32(v);
                m2 += v * (s_c[b][o] / fmaxf(rs, 1e-12f));
            }
            s_m2[b][lane] = m2;
        } else {
            const int wloc = warp - 16;
#pragma unroll
            for (int bb2 = 0; bb2 < 2; bb2++) {
                const int b = wloc * 2 + bb2;
                float m1 = 0.f;
#pragma unroll
                for (int ii = 0; ii < 4; ii++) {
                    float v  = s_I[b][ii * 32 + lane];
                    float rs = wsum32(v);
                    m1 += s_featD[ii][b].x * v / fmaxf(rs, 1e-12f);
                }
                s_m1[b][lane] = m1;
            }
        }
        __syncthreads();

        // P4: combine, MR gate, LN, outputs, new carry
        if (warp < 8) {
            const int b = warp;
            float mn = s_m1[b][lane] + s_m2[b][lane];
            float o  = s_go[b][lane];
            float f  = 1.f - o;
            float x  = s_ov1[b][lane];
            float mu = wsum32(x) * (1.f / 32.f);
            float d  = x - mu;
            float var = wsum32(d * d) * (1.f / 32.f);
            float ln  = d * rsqrtf(var + 1e-5f) * r_lng + r_lnb;
            float ov2 = ln - fmaxf(ln - f, 0.f);
            float MR  = fmaxf(ov2 + 1.f - f, 0.f) + f - 1.f;
            float op  = o + MR;
            float h   = o * mn;
            float cn  = (1.f - op) * mn;
            float mf  = MR * mn;
            size_t idx = (size_t)t * BATCH * OUTDIM + (size_t)(cta * BC + b) * OUTDIM + lane;
            out_h[idx] = h;  out_c[idx] = cn; out_o[idx] = o;  out_mr[idx] = MR;
            out_op[idx] = op; out_mf[idx] = mf; out_of[idx] = h;
            s_c[b][lane] = cn;
            float as = wsum32(fabsf(cn));
            if (lane == 0) s_abs[b] = as;
        }
        __syncthreads();
        // post this CTA's |c_new| partial for step t+1 (tag+value, one store)
        if (tid == 0) {
            float p = 0.f;
#pragma unroll
            for (int b = 0; b < 8; b++) p += s_abs[b];
            ull pk = ((ull)(unsigned)(t + 2) << 32) | (ull)__float_as_uint(p);
            post_slot(g_slot + (size_t)(t + 1) * NCTA + cta, pk);
        }
    }
}

// ---------------- launch ------------------------------------------------------
extern "C" void kernel_launch(void* const* d_in, const int* in_sizes, int n_in,
                              void* d_out, int out_size) {
    const float* xm  = (const float*)d_in[0];
    const float* xa  = (const float*)d_in[1];
    const float* Wi  = (const float*)d_in[2];
    const float* bi  = (const float*)d_in[3];
    const float* Wr  = (const float*)d_in[4];
    const float* br  = (const float*)d_in[5];
    const float* Wo  = (const float*)d_in[6];
    const float* bo  = (const float*)d_in[7];
    const float* Ws  = (const float*)d_in[8];
    const float* Wrm = (const float*)d_in[9];
    const float* b0  = (const float*)d_in[10];
    const float* lng = (const float*)d_in[11];
    const float* lnb = (const float*)d_in[12];
    (void)in_sizes; (void)n_in; (void)out_size;

    prep_kernel<<<128, 256>>>(Wi, bi, Wr, br, Wo, bo, Ws, Wrm, b0);
    lstm_kernel<<<NCTA, NTHREADS>>>(xm, xa, lng, lnb, (float*)d_out);
}